// round 2
// baseline (speedup 1.0000x reference)
#include <cuda_runtime.h>
#include <math.h>

#define S 2048
#define E 512
#define HD 512
#define G4 2048   /* 4*HD */
#define NT 12     /* tags */
#define NDIRCTA 64

// ---------------- scratch (device globals; no runtime allocation) ----------
__device__ float g_xp[2][S][G4];     // input projections + bias, both dirs (32 MB)
__device__ float g_hs[2][S][HD];     // hidden states, both dirs (8 MB)
__device__ float g_feats[S][NT];     // emission features
__device__ int   g_cnt[2][S];        // per-step arrival counters

// ---------------------------------------------------------------------------
__global__ void zero_cnt_kernel() {
    int i = blockIdx.x * blockDim.x + threadIdx.x;
    if (i < 2 * S) ((int*)g_cnt)[i] = 0;
}

// ---------------- xproj GEMM: C[t][row] = x[t] . Wih[row] + b[row] ---------
// BM=BN=128, BK=16, 256 threads, 8x8 microtile
__global__ void __launch_bounds__(256) xproj_kernel(
    const int* __restrict__ sentence, const float* __restrict__ emb,
    const float* __restrict__ wih_f, const float* __restrict__ b_f,
    const float* __restrict__ wih_b, const float* __restrict__ b_b)
{
    __shared__ float As[16][128];
    __shared__ float Bs[16][128];

    const int dir = blockIdx.z;
    const float* __restrict__ wih  = dir ? wih_b : wih_f;
    const float* __restrict__ bias = dir ? b_b  : b_f;
    const int m0 = blockIdx.y * 128;   // t tile
    const int n0 = blockIdx.x * 128;   // gate-row tile
    const int tid = threadIdx.x;

    const int lr = tid >> 1;           // 0..127
    const int lk = (tid & 1) * 8;      // 0 or 8
    const float* arow = emb + (size_t)sentence[m0 + lr] * E + lk;
    const float* brow = wih + (size_t)(n0 + lr) * E + lk;

    const int tx = tid & 15, ty = tid >> 4;
    float acc[8][8];
#pragma unroll
    for (int i = 0; i < 8; i++)
#pragma unroll
        for (int j = 0; j < 8; j++) acc[i][j] = 0.f;

    for (int k0 = 0; k0 < E; k0 += 16) {
        float4 a0 = *(const float4*)(arow + k0);
        float4 a1 = *(const float4*)(arow + k0 + 4);
        float4 b0 = *(const float4*)(brow + k0);
        float4 b1 = *(const float4*)(brow + k0 + 4);
        __syncthreads();
        As[lk + 0][lr] = a0.x; As[lk + 1][lr] = a0.y; As[lk + 2][lr] = a0.z; As[lk + 3][lr] = a0.w;
        As[lk + 4][lr] = a1.x; As[lk + 5][lr] = a1.y; As[lk + 6][lr] = a1.z; As[lk + 7][lr] = a1.w;
        Bs[lk + 0][lr] = b0.x; Bs[lk + 1][lr] = b0.y; Bs[lk + 2][lr] = b0.z; Bs[lk + 3][lr] = b0.w;
        Bs[lk + 4][lr] = b1.x; Bs[lk + 5][lr] = b1.y; Bs[lk + 6][lr] = b1.z; Bs[lk + 7][lr] = b1.w;
        __syncthreads();
#pragma unroll
        for (int kk = 0; kk < 16; kk++) {
            float a[8], b[8];
            *(float4*)&a[0] = *(const float4*)&As[kk][ty * 8];
            *(float4*)&a[4] = *(const float4*)&As[kk][ty * 8 + 4];
            *(float4*)&b[0] = *(const float4*)&Bs[kk][tx * 8];
            *(float4*)&b[4] = *(const float4*)&Bs[kk][tx * 8 + 4];
#pragma unroll
            for (int i = 0; i < 8; i++)
#pragma unroll
                for (int j = 0; j < 8; j++)
                    acc[i][j] = fmaf(a[i], b[j], acc[i][j]);
        }
    }

    float bv[8];
#pragma unroll
    for (int j = 0; j < 8; j++) bv[j] = bias[n0 + tx * 8 + j];
#pragma unroll
    for (int i = 0; i < 8; i++) {
        const int m = m0 + ty * 8 + i;
        float4 o0, o1;
        o0.x = acc[i][0] + bv[0]; o0.y = acc[i][1] + bv[1];
        o0.z = acc[i][2] + bv[2]; o0.w = acc[i][3] + bv[3];
        o1.x = acc[i][4] + bv[4]; o1.y = acc[i][5] + bv[5];
        o1.z = acc[i][6] + bv[6]; o1.w = acc[i][7] + bv[7];
        *(float4*)&g_xp[dir][m][n0 + tx * 8]     = o0;
        *(float4*)&g_xp[dir][m][n0 + tx * 8 + 4] = o1;
    }
}

// ---------------- persistent bidirectional LSTM ----------------------------
// grid = 128 CTAs (64/dir), 256 threads (8 warps). warp w owns h-index
// cid*8+w; each lane holds 4x16 Whh weights in registers.
// Accurate math in the serial epilogue (error compounds over 2048 steps).
__device__ __forceinline__ float sigmoid_acc(float x) {
    return 1.0f / (1.0f + expf(-x));
}

__global__ void __launch_bounds__(256, 1) lstm_kernel(
    const float* __restrict__ whh_f, const float* __restrict__ whh_b,
    const float* __restrict__ h0, const float* __restrict__ c0)
{
    const int dir  = blockIdx.x & 1;
    const int cid  = blockIdx.x >> 1;          // 0..63
    const int warp = threadIdx.x >> 5;         // 0..7
    const int lane = threadIdx.x & 31;
    const int hidx = cid * 8 + warp;           // 0..511

    const float* __restrict__ whh = dir ? whh_b : whh_f;

    float wr[4][16];
#pragma unroll
    for (int gg = 0; gg < 4; gg++) {
        const float* r = whh + (size_t)(gg * HD + hidx) * HD + lane * 16;
#pragma unroll
        for (int q = 0; q < 4; q++) {
            float4 v = *(const float4*)(r + q * 4);
            wr[gg][q * 4 + 0] = v.x; wr[gg][q * 4 + 1] = v.y;
            wr[gg][q * 4 + 2] = v.z; wr[gg][q * 4 + 3] = v.w;
        }
    }
    float c = c0[dir * HD + hidx];

    int t = dir ? (S - 1) : 0;
    const int dt = dir ? -1 : 1;

    for (int s = 0; s < S; s++, t += dt) {
        // prefetch the 4 gate pre-activations (issued before the wait)
        float xv = 0.0f;
        if (lane < 4) xv = g_xp[dir][t][lane * HD + hidx];

        const float* hp;
        if (s == 0) {
            hp = h0 + dir * HD;
        } else {
            const int tp = t - dt;
            if (threadIdx.x == 0) {
                const int* cp = &g_cnt[dir][tp];
                int v;
                do {
                    asm volatile("ld.acquire.gpu.global.b32 %0, [%1];"
                                 : "=r"(v) : "l"(cp) : "memory");
                } while (v < NDIRCTA);
            }
            __syncthreads();
            hp = &g_hs[dir][tp][0];
        }

        float hv[16];
#pragma unroll
        for (int q = 0; q < 4; q++) {
            float4 v = *(const float4*)(hp + lane * 16 + q * 4);
            hv[q * 4 + 0] = v.x; hv[q * 4 + 1] = v.y;
            hv[q * 4 + 2] = v.z; hv[q * 4 + 3] = v.w;
        }

        float a0 = 0.f, a1 = 0.f, a2 = 0.f, a3 = 0.f;
#pragma unroll
        for (int k = 0; k < 16; k++) {
            a0 = fmaf(hv[k], wr[0][k], a0);
            a1 = fmaf(hv[k], wr[1][k], a1);
            a2 = fmaf(hv[k], wr[2][k], a2);
            a3 = fmaf(hv[k], wr[3][k], a3);
        }
#pragma unroll
        for (int off = 16; off > 0; off >>= 1) {
            a0 += __shfl_xor_sync(0xFFFFFFFFu, a0, off);
            a1 += __shfl_xor_sync(0xFFFFFFFFu, a1, off);
            a2 += __shfl_xor_sync(0xFFFFFFFFu, a2, off);
            a3 += __shfl_xor_sync(0xFFFFFFFFu, a3, off);
        }
        const float xi = __shfl_sync(0xFFFFFFFFu, xv, 0);
        const float xf = __shfl_sync(0xFFFFFFFFu, xv, 1);
        const float xg = __shfl_sync(0xFFFFFFFFu, xv, 2);
        const float xo = __shfl_sync(0xFFFFFFFFu, xv, 3);

        if (lane == 0) {
            const float ig = sigmoid_acc(a0 + xi);
            const float fg = sigmoid_acc(a1 + xf);
            const float tg = tanhf(a2 + xg);
            const float og = sigmoid_acc(a3 + xo);
            c = fg * c + ig * tg;
            g_hs[dir][t][hidx] = og * tanhf(c);
        }
        __syncthreads();
        if (threadIdx.x == 0) {
            __threadfence();
            asm volatile("red.release.gpu.global.add.s32 [%0], %1;"
                         :: "l"(&g_cnt[dir][t]), "r"(1) : "memory");
        }
    }
}

// ---------------- feats: [S, NT] = [hf|hb] @ w_out^T + b_out ---------------
__global__ void feats_kernel(const float* __restrict__ w_out,
                             const float* __restrict__ b_out)
{
    const int t = blockIdx.x;
    const int tid = threadIdx.x;   // 128
    float par[NT];
#pragma unroll
    for (int g = 0; g < NT; g++) par[g] = 0.f;

    for (int j = tid; j < HD; j += 128) {
        const float hf = g_hs[0][t][j];
        const float hb = g_hs[1][t][j];
#pragma unroll
        for (int g = 0; g < NT; g++)
            par[g] += hf * w_out[g * 1024 + j] + hb * w_out[g * 1024 + HD + j];
    }
#pragma unroll
    for (int off = 16; off > 0; off >>= 1)
#pragma unroll
        for (int g = 0; g < NT; g++)
            par[g] += __shfl_xor_sync(0xFFFFFFFFu, par[g], off);

    __shared__ float sm[NT][4];
    if ((tid & 31) == 0)
#pragma unroll
        for (int g = 0; g < NT; g++) sm[g][tid >> 5] = par[g];
    __syncthreads();
    if (tid < NT)
        g_feats[t][tid] = sm[tid][0] + sm[tid][1] + sm[tid][2] + sm[tid][3] + b_out[tid];
}

// ---------------- CRF: forward scan + gold score ---------------------------
// warp0: 12-lane forward algorithm. Rebase by the per-step MAX over live
// lanes (keeps live values near 0 in fp32; dead lanes underflow identically
// to the reference). Running offset kept in double. Accurate expf/logf.
// warp1: gold path score (double accumulation)
__global__ void crf_kernel(const float* __restrict__ trans,
                           const int* __restrict__ gold_tags,
                           float* __restrict__ out)
{
    const int tid = threadIdx.x;    // 64 threads
    __shared__ double s_gold;
    __shared__ double s_alpha;

    if (tid >= 32) {
        // gold score
        const int lane = tid - 32;
        double acc = 0.0;
        for (int t = lane; t < S; t += 32) {
            const int tc = gold_tags[t];
            const int tp = (t == 0) ? 0 /*START*/ : gold_tags[t - 1];
            acc += (double)trans[tc * NT + tp] + (double)g_feats[t][tc];
        }
#pragma unroll
        for (int off = 16; off > 0; off >>= 1)
            acc += __shfl_xor_sync(0xFFFFFFFFu, acc, off);
        if (lane == 0)
            s_gold = acc + (double)trans[1 * NT + gold_tags[S - 1]];  // END=1
    } else {
        const int i = tid;
        const bool act = (i < NT);
        float tr[NT];
#pragma unroll
        for (int j = 0; j < NT; j++)
            tr[j] = act ? trans[i * NT + j] : -1e30f;

        float prev = (i == 0) ? 0.f : -1e6f;   // START=0 gets 0, rest NEG
        double base = 0.0;                      // running offset (uniform)
        for (int t = 0; t < S; t++) {
            const float feat = act ? g_feats[t][i] : 0.f;
            float m = -3.0e38f;
            float v[NT];
#pragma unroll
            for (int j = 0; j < NT; j++) {
                v[j] = __shfl_sync(0xFFFFFFFFu, prev, j) + tr[j];
                m = fmaxf(m, v[j]);
            }
            float ssum = 0.f;
#pragma unroll
            for (int j = 0; j < NT; j++)
                ssum += expf(v[j] - m);
            float pn = feat + m + logf(ssum);
            // rebase by the max over ACTIVE lanes: live values stay O(1)
            float d = act ? pn : -3.0e38f;
#pragma unroll
            for (int off = 16; off > 0; off >>= 1)
                d = fmaxf(d, __shfl_xor_sync(0xFFFFFFFFu, d, off));
            prev = pn - d;
            base += (double)d;
        }
        // alpha = base + logsumexp_i(prev_rel[i] + trans[END][i])
        float fv = act ? (prev + trans[1 * NT + i]) : -3.0e38f;
        float m = fv;
#pragma unroll
        for (int off = 16; off > 0; off >>= 1)
            m = fmaxf(m, __shfl_xor_sync(0xFFFFFFFFu, m, off));
        float e = act ? expf(fv - m) : 0.f;
#pragma unroll
        for (int off = 16; off > 0; off >>= 1)
            e += __shfl_xor_sync(0xFFFFFFFFu, e, off);
        if (tid == 0)
            s_alpha = base + (double)m + log((double)e);
    }
    __syncthreads();
    if (tid == 0)
        out[0] = (float)(s_alpha - s_gold);
}

// ---------------------------------------------------------------------------
extern "C" void kernel_launch(void* const* d_in, const int* in_sizes, int n_in,
                              void* d_out, int out_size)
{
    const int*   sentence = (const int*)  d_in[0];
    const int*   gold     = (const int*)  d_in[1];
    const float* emb      = (const float*)d_in[2];
    const float* wih_f    = (const float*)d_in[3];
    const float* whh_f    = (const float*)d_in[4];
    const float* b_f      = (const float*)d_in[5];
    const float* wih_b    = (const float*)d_in[6];
    const float* whh_b    = (const float*)d_in[7];
    const float* b_b      = (const float*)d_in[8];
    const float* w_out    = (const float*)d_in[9];
    const float* b_out    = (const float*)d_in[10];
    const float* trans    = (const float*)d_in[11];
    const float* h0       = (const float*)d_in[12];
    const float* c0       = (const float*)d_in[13];
    float* out = (float*)d_out;

    zero_cnt_kernel<<<16, 256>>>();

    dim3 gg(G4 / 128, S / 128, 2);
    xproj_kernel<<<gg, 256>>>(sentence, emb, wih_f, b_f, wih_b, b_b);

    lstm_kernel<<<128, 256>>>(whh_f, whh_b, h0, c0);

    feats_kernel<<<S, 128>>>(w_out, b_out);

    crf_kernel<<<1, 64>>>(trans, gold, out);
}

// round 5
// speedup vs baseline: 1.1647x; 1.1647x over previous
#include <cuda_runtime.h>
#include <math.h>

#define S 2048
#define E 512
#define HD 512
#define G4 2048   /* 4*HD */
#define NT 12     /* tags */
#define NDIRCTA 64

// ---------------- scratch (device globals; no runtime allocation) ----------
__device__ float g_xp[2][S][G4];     // input projections + bias, both dirs (32 MB)
__device__ float g_hs[2][S][HD];     // hidden states, both dirs (8 MB)
__device__ float g_feats[S][NT];     // emission features
__device__ int   g_cnt[2][S];        // per-step arrival counters

// ---------------------------------------------------------------------------
__global__ void zero_cnt_kernel() {
    int i = blockIdx.x * blockDim.x + threadIdx.x;
    if (i < 2 * S) ((int*)g_cnt)[i] = 0;
}

// ---------------- xproj GEMM: C[t][row] = x[t] . Wih[row] + b[row] ---------
// BM=BN=128, BK=16, 256 threads, 8x8 microtile
__global__ void __launch_bounds__(256) xproj_kernel(
    const int* __restrict__ sentence, const float* __restrict__ emb,
    const float* __restrict__ wih_f, const float* __restrict__ b_f,
    const float* __restrict__ wih_b, const float* __restrict__ b_b)
{
    __shared__ float As[16][128];
    __shared__ float Bs[16][128];

    const int dir = blockIdx.z;
    const float* __restrict__ wih  = dir ? wih_b : wih_f;
    const float* __restrict__ bias = dir ? b_b  : b_f;
    const int m0 = blockIdx.y * 128;   // t tile
    const int n0 = blockIdx.x * 128;   // gate-row tile
    const int tid = threadIdx.x;

    const int lr = tid >> 1;           // 0..127
    const int lk = (tid & 1) * 8;      // 0 or 8
    const float* arow = emb + (size_t)sentence[m0 + lr] * E + lk;
    const float* brow = wih + (size_t)(n0 + lr) * E + lk;

    const int tx = tid & 15, ty = tid >> 4;
    float acc[8][8];
#pragma unroll
    for (int i = 0; i < 8; i++)
#pragma unroll
        for (int j = 0; j < 8; j++) acc[i][j] = 0.f;

    for (int k0 = 0; k0 < E; k0 += 16) {
        float4 a0 = *(const float4*)(arow + k0);
        float4 a1 = *(const float4*)(arow + k0 + 4);
        float4 b0 = *(const float4*)(brow + k0);
        float4 b1 = *(const float4*)(brow + k0 + 4);
        __syncthreads();
        As[lk + 0][lr] = a0.x; As[lk + 1][lr] = a0.y; As[lk + 2][lr] = a0.z; As[lk + 3][lr] = a0.w;
        As[lk + 4][lr] = a1.x; As[lk + 5][lr] = a1.y; As[lk + 6][lr] = a1.z; As[lk + 7][lr] = a1.w;
        Bs[lk + 0][lr] = b0.x; Bs[lk + 1][lr] = b0.y; Bs[lk + 2][lr] = b0.z; Bs[lk + 3][lr] = b0.w;
        Bs[lk + 4][lr] = b1.x; Bs[lk + 5][lr] = b1.y; Bs[lk + 6][lr] = b1.z; Bs[lk + 7][lr] = b1.w;
        __syncthreads();
#pragma unroll
        for (int kk = 0; kk < 16; kk++) {
            float a[8], b[8];
            *(float4*)&a[0] = *(const float4*)&As[kk][ty * 8];
            *(float4*)&a[4] = *(const float4*)&As[kk][ty * 8 + 4];
            *(float4*)&b[0] = *(const float4*)&Bs[kk][tx * 8];
            *(float4*)&b[4] = *(const float4*)&Bs[kk][tx * 8 + 4];
#pragma unroll
            for (int i = 0; i < 8; i++)
#pragma unroll
                for (int j = 0; j < 8; j++)
                    acc[i][j] = fmaf(a[i], b[j], acc[i][j]);
        }
    }

    float bv[8];
#pragma unroll
    for (int j = 0; j < 8; j++) bv[j] = bias[n0 + tx * 8 + j];
#pragma unroll
    for (int i = 0; i < 8; i++) {
        const int m = m0 + ty * 8 + i;
        float4 o0, o1;
        o0.x = acc[i][0] + bv[0]; o0.y = acc[i][1] + bv[1];
        o0.z = acc[i][2] + bv[2]; o0.w = acc[i][3] + bv[3];
        o1.x = acc[i][4] + bv[4]; o1.y = acc[i][5] + bv[5];
        o1.z = acc[i][6] + bv[6]; o1.w = acc[i][7] + bv[7];
        *(float4*)&g_xp[dir][m][n0 + tx * 8]     = o0;
        *(float4*)&g_xp[dir][m][n0 + tx * 8 + 4] = o1;
    }
}

// ---------------- persistent bidirectional LSTM ----------------------------
// grid = 128 CTAs (64/dir), 256 threads (8 warps). warp w owns h-index
// cid*8+w; each lane holds 4x16 Whh weights in registers.
// Fast-math activations (safe: R1's error was the CRF rebase, not this).
__device__ __forceinline__ float sigmoid_f(float x) {
    return __fdividef(1.0f, 1.0f + __expf(-x));
}
__device__ __forceinline__ float tanh_f(float x) {
    // 1 - 2/(e^{2x}+1)
    return 1.0f - 2.0f * __fdividef(1.0f, 1.0f + __expf(2.0f * x));
}

__global__ void __launch_bounds__(256, 1) lstm_kernel(
    const float* __restrict__ whh_f, const float* __restrict__ whh_b,
    const float* __restrict__ h0, const float* __restrict__ c0)
{
    const int dir  = blockIdx.x & 1;
    const int cid  = blockIdx.x >> 1;          // 0..63
    const int warp = threadIdx.x >> 5;         // 0..7
    const int lane = threadIdx.x & 31;
    const int hidx = cid * 8 + warp;           // 0..511

    const float* __restrict__ whh = dir ? whh_b : whh_f;

    float wr[4][16];
#pragma unroll
    for (int gg = 0; gg < 4; gg++) {
        const float* r = whh + (size_t)(gg * HD + hidx) * HD + lane * 16;
#pragma unroll
        for (int q = 0; q < 4; q++) {
            float4 v = *(const float4*)(r + q * 4);
            wr[gg][q * 4 + 0] = v.x; wr[gg][q * 4 + 1] = v.y;
            wr[gg][q * 4 + 2] = v.z; wr[gg][q * 4 + 3] = v.w;
        }
    }
    float c = c0[dir * HD + hidx];   // replicated on all lanes

    int t = dir ? (S - 1) : 0;
    const int dt = dir ? -1 : 1;

    for (int s = 0; s < S; s++, t += dt) {
        // prefetch this lane's gate pre-activation (lane k<4 -> gate k)
        float xv = 0.0f;
        if (lane < 4) xv = g_xp[dir][t][lane * HD + hidx];

        const float* hp;
        if (s == 0) {
            hp = h0 + dir * HD;
        } else {
            const int tp = t - dt;
            // every warp polls (coalesced broadcast load, 1 request/warp)
            const int* cp = &g_cnt[dir][tp];
            int v;
            do {
                asm volatile("ld.acquire.gpu.global.b32 %0, [%1];"
                             : "=r"(v) : "l"(cp) : "memory");
            } while (v < NDIRCTA);
            hp = &g_hs[dir][tp][0];
        }

        float hv[16];
#pragma unroll
        for (int q = 0; q < 4; q++) {
            float4 v = *(const float4*)(hp + lane * 16 + q * 4);
            hv[q * 4 + 0] = v.x; hv[q * 4 + 1] = v.y;
            hv[q * 4 + 2] = v.z; hv[q * 4 + 3] = v.w;
        }

        float a0 = 0.f, a1 = 0.f, a2 = 0.f, a3 = 0.f;
#pragma unroll
        for (int k = 0; k < 16; k++) {
            a0 = fmaf(hv[k], wr[0][k], a0);
            a1 = fmaf(hv[k], wr[1][k], a1);
            a2 = fmaf(hv[k], wr[2][k], a2);
            a3 = fmaf(hv[k], wr[3][k], a3);
        }
#pragma unroll
        for (int off = 16; off > 0; off >>= 1) {
            a0 += __shfl_xor_sync(0xFFFFFFFFu, a0, off);
            a1 += __shfl_xor_sync(0xFFFFFFFFu, a1, off);
            a2 += __shfl_xor_sync(0xFFFFFFFFu, a2, off);
            a3 += __shfl_xor_sync(0xFFFFFFFFu, a3, off);
        }

        // gates distributed: lane k (k<4) computes activation of gate k with
        // its own x pre-activation (no shuffle needed to assemble input)
        const float pre = ((lane == 0) ? a0 : (lane == 1) ? a1
                          : (lane == 2) ? a2 : a3) + xv;
        const float sg = sigmoid_f(pre);
        const float th = tanh_f(pre);
        const float act = (lane == 2) ? th : sg;

        const float ig = __shfl_sync(0xFFFFFFFFu, act, 0);
        const float fg = __shfl_sync(0xFFFFFFFFu, act, 1);
        const float tg = __shfl_sync(0xFFFFFFFFu, act, 2);
        const float og = __shfl_sync(0xFFFFFFFFu, act, 3);

        c = fg * c + ig * tg;                 // replicated on all lanes
        const float hvout = og * tanh_f(c);
        if (lane == 0) g_hs[dir][t][hidx] = hvout;

        __syncthreads();                      // order all 8 warps' h stores
        if (threadIdx.x == 0) {
            // release is cumulative over bar-ordered writes (CG grid.sync pattern)
            asm volatile("red.release.gpu.global.add.s32 [%0], %1;"
                         :: "l"(&g_cnt[dir][t]), "r"(1) : "memory");
        }
    }
}

// ---------------- feats: [S, NT] = [hf|hb] @ w_out^T + b_out ---------------
__global__ void feats_kernel(const float* __restrict__ w_out,
                             const float* __restrict__ b_out)
{
    const int t = blockIdx.x;
    const int tid = threadIdx.x;   // 128
    float par[NT];
#pragma unroll
    for (int g = 0; g < NT; g++) par[g] = 0.f;

    for (int j = tid; j < HD; j += 128) {
        const float hf = g_hs[0][t][j];
        const float hb = g_hs[1][t][j];
#pragma unroll
        for (int g = 0; g < NT; g++)
            par[g] += hf * w_out[g * 1024 + j] + hb * w_out[g * 1024 + HD + j];
    }
#pragma unroll
    for (int off = 16; off > 0; off >>= 1)
#pragma unroll
        for (int g = 0; g < NT; g++)
            par[g] += __shfl_xor_sync(0xFFFFFFFFu, par[g], off);

    __shared__ float sm[NT][4];
    if ((tid & 31) == 0)
#pragma unroll
        for (int g = 0; g < NT; g++) sm[g][tid >> 5] = par[g];
    __syncthreads();
    if (tid < NT)
        g_feats[t][tid] = sm[tid][0] + sm[tid][1] + sm[tid][2] + sm[tid][3] + b_out[tid];
}

// ---------------- CRF: forward scan + gold score ---------------------------
// warp0: 12-lane forward algorithm. Rebase by per-step MAX over live lanes;
// running offset in double. Fast __expf/__logf (values kept near 0 by rebase).
// warp1: gold path score (double accumulation)
__global__ void crf_kernel(const float* __restrict__ trans,
                           const int* __restrict__ gold_tags,
                           float* __restrict__ out)
{
    const int tid = threadIdx.x;    // 64 threads
    __shared__ double s_gold;
    __shared__ double s_alpha;

    if (tid >= 32) {
        // gold score
        const int lane = tid - 32;
        double acc = 0.0;
        for (int t = lane; t < S; t += 32) {
            const int tc = gold_tags[t];
            const int tp = (t == 0) ? 0 /*START*/ : gold_tags[t - 1];
            acc += (double)trans[tc * NT + tp] + (double)g_feats[t][tc];
        }
#pragma unroll
        for (int off = 16; off > 0; off >>= 1)
            acc += __shfl_xor_sync(0xFFFFFFFFu, acc, off);
        if (lane == 0)
            s_gold = acc + (double)trans[1 * NT + gold_tags[S - 1]];  // END=1
    } else {
        const int i = tid;
        const bool act = (i < NT);
        float tr[NT];
#pragma unroll
        for (int j = 0; j < NT; j++)
            tr[j] = act ? trans[i * NT + j] : -1e30f;

        float prev = (i == 0) ? 0.f : -1e6f;   // START=0 gets 0, rest NEG
        double base = 0.0;                      // running offset (uniform)
        for (int t = 0; t < S; t++) {
            const float feat = act ? g_feats[t][i] : 0.f;
            float m = -3.0e38f;
            float v[NT];
#pragma unroll
            for (int j = 0; j < NT; j++) {
                v[j] = __shfl_sync(0xFFFFFFFFu, prev, j) + tr[j];
                m = fmaxf(m, v[j]);
            }
            float ssum = 0.f;
#pragma unroll
            for (int j = 0; j < NT; j++)
                ssum += __expf(v[j] - m);
            float pn = feat + m + __logf(ssum);
            // rebase by the max over ACTIVE lanes: live values stay O(1)
            float d = act ? pn : -3.0e38f;
#pragma unroll
            for (int off = 16; off > 0; off >>= 1)
                d = fmaxf(d, __shfl_xor_sync(0xFFFFFFFFu, d, off));
            prev = pn - d;
            base += (double)d;
        }
        // alpha = base + logsumexp_i(prev_rel[i] + trans[END][i])
        float fv = act ? (prev + trans[1 * NT + i]) : -3.0e38f;
        float m = fv;
#pragma unroll
        for (int off = 16; off > 0; off >>= 1)
            m = fmaxf(m, __shfl_xor_sync(0xFFFFFFFFu, m, off));
        float e = act ? __expf(fv - m) : 0.f;
#pragma unroll
        for (int off = 16; off > 0; off >>= 1)
            e += __shfl_xor_sync(0xFFFFFFFFu, e, off);
        if (tid == 0)
            s_alpha = base + (double)m + log((double)e);
    }
    __syncthreads();
    if (tid == 0)
        out[0] = (float)(s_alpha - s_gold);
}

// ---------------------------------------------------------------------------
extern "C" void kernel_launch(void* const* d_in, const int* in_sizes, int n_in,
                              void* d_out, int out_size)
{
    const int*   sentence = (const int*)  d_in[0];
    const int*   gold     = (const int*)  d_in[1];
    const float* emb      = (const float*)d_in[2];
    const float* wih_f    = (const float*)d_in[3];
    const float* whh_f    = (const float*)d_in[4];
    const float* b_f      = (const float*)d_in[5];
    const float* wih_b    = (const float*)d_in[6];
    const float* whh_b    = (const float*)d_in[7];
    const float* b_b      = (const float*)d_in[8];
    const float* w_out    = (const float*)d_in[9];
    const float* b_out    = (const float*)d_in[10];
    const float* trans    = (const float*)d_in[11];
    const float* h0       = (const float*)d_in[12];
    const float* c0       = (const float*)d_in[13];
    float* out = (float*)d_out;

    zero_cnt_kernel<<<16, 256>>>();

    dim3 gg(G4 / 128, S / 128, 2);
    xproj_kernel<<<gg, 256>>>(sentence, emb, wih_f, b_f, wih_b, b_b);

    lstm_kernel<<<128, 256>>>(whh_f, whh_b, h0, c0);

    feats_kernel<<<S, 128>>>(w_out, b_out);

    crf_kernel<<<1, 64>>>(trans, gold, out);
}